// round 16
// baseline (speedup 1.0000x reference)
#include <cuda_runtime.h>
#include <cuda_fp16.h>
#include <cstdint>

#define BB 256
#define NN 256
#define IND 64
#define HID 128
#define NOUT 16
#define NL 3
#define NK 4
#define MM (BB*NN)
#define LN_EPS 1e-5f
#define EP 136
#define EPB (EP*2)

__device__ uint16_t g_yhi[(size_t)MM * HID];
__device__ uint16_t g_ylo[(size_t)MM * HID];
__device__ uint16_t g_xhi[(size_t)MM * HID];
__device__ uint16_t g_xlo[(size_t)MM * HID];
__device__ uint16_t g_fhi[(size_t)MM * IND];
__device__ uint16_t g_flo[(size_t)MM * IND];
__device__ uint16_t g_ewh[(size_t)NK * HID * HID];
__device__ uint16_t g_nwh[(size_t)NL * HID * HID];
__device__ uint16_t g_nwl[(size_t)NL * HID * HID];
__device__ float    g_ebsum[HID];
__device__ float    g_repr[(size_t)BB * HID];

__device__ __forceinline__ void splith(float a, uint16_t &h, uint16_t &l) {
    __half hh = __float2half_rn(a);
    __half ll = __float2half_rn(a - __half2float(hh));
    h = __half_as_ushort(hh); l = __half_as_ushort(ll);
}
__device__ __forceinline__ uint32_t packu(uint16_t a, uint16_t b) {
    return (uint32_t)a | ((uint32_t)b << 16);
}
__device__ __forceinline__ uint32_t f22h2(float x, float y) {
    __half2 h = __floats2half2_rn(x, y);
    return *(uint32_t*)&h;
}
__device__ __forceinline__ float2 h2pairf(uint32_t hbits, uint32_t lbits) {
    float2 a = __half22float2(*(__half2*)&hbits);
    float2 b = __half22float2(*(__half2*)&lbits);
    return make_float2(a.x + b.x, a.y + b.y);
}
__device__ __forceinline__ uint32_t cvta_s(const void* p) {
    return (uint32_t)__cvta_generic_to_shared(p);
}
__device__ __forceinline__ void ldsm_x4(uint32_t* r, uint32_t addr) {
    asm volatile("ldmatrix.sync.aligned.m8n8.x4.shared.b16 {%0,%1,%2,%3}, [%4];"
                 : "=r"(r[0]), "=r"(r[1]), "=r"(r[2]), "=r"(r[3]) : "r"(addr));
}
__device__ __forceinline__ void ldsm_x4_t(uint32_t* r, uint32_t addr) {
    asm volatile("ldmatrix.sync.aligned.m8n8.x4.trans.shared.b16 {%0,%1,%2,%3}, [%4];"
                 : "=r"(r[0]), "=r"(r[1]), "=r"(r[2]), "=r"(r[3]) : "r"(addr));
}
__device__ __forceinline__ void mma_f16(float* c, const uint32_t* a, const uint32_t* b) {
    asm volatile("mma.sync.aligned.m16n8k16.row.col.f32.f16.f16.f32 "
                 "{%0,%1,%2,%3}, {%4,%5,%6,%7}, {%8,%9}, {%0,%1,%2,%3};"
                 : "+f"(c[0]), "+f"(c[1]), "+f"(c[2]), "+f"(c[3])
                 : "r"(a[0]), "r"(a[1]), "r"(a[2]), "r"(a[3]), "r"(b[0]), "r"(b[1]));
}
__device__ __forceinline__ void cp16(uint32_t dst, const void* src) {
    asm volatile("cp.async.cg.shared.global [%0], [%1], 16;" :: "r"(dst), "l"(src));
}
#define CP_COMMIT() asm volatile("cp.async.commit_group;")
#define CP_WAIT(n)  asm volatile("cp.async.wait_group %0;" :: "n"(n))

// ---------------------------------------------------------------------------------------
__global__ void prep_weights(const float* __restrict__ nW0, const float* __restrict__ nW1,
                             const float* __restrict__ nW2, const float* __restrict__ eW,
                             uint16_t* __restrict__ nwh, uint16_t* __restrict__ nwl,
                             uint16_t* __restrict__ ewh)
{
    const int bid = blockIdx.x, tid = threadIdx.x;
    if (bid < 32) {
        const int idx = bid * 256 + tid;
        const int o = idx >> 6, d = idx & 63;
        uint16_t h, l; splith(nW0[idx], h, l);
        nwh[d * 128 + o] = h; nwl[d * 128 + o] = l;
    } else if (bid < 96) {
        const int idx = (bid - 32) * 256 + tid;
        const int o = idx >> 7, d = idx & 127;
        uint16_t h, l; splith(nW1[idx], h, l);
        nwh[16384 + d * 128 + o] = h; nwl[16384 + d * 128 + o] = l;
    } else if (bid < 160) {
        const int idx = (bid - 96) * 256 + tid;
        const int o = idx >> 7, d = idx & 127;
        uint16_t h, l; splith(nW2[idx], h, l);
        nwh[32768 + d * 128 + o] = h; nwl[32768 + d * 128 + o] = l;
    } else {
        const int idx = (bid - 160) * 256 + tid;
        const int k = idx >> 14, rem = idx & 16383;
        const int o = rem >> 7, d = rem & 127;
        ewh[(k << 14) + d * 128 + o] = __half_as_ushort(__float2half_rn(eW[idx]));
    }
}

__global__ void prep_feat(const float* __restrict__ f, uint16_t* __restrict__ hi,
                          uint16_t* __restrict__ lo)
{
    const int idx = blockIdx.x * 256 + threadIdx.x;
    uint16_t h, l;
    splith(f[idx], h, l);
    hi[idx] = h; lo[idx] = l;
}

__global__ void prep_misc(const float* __restrict__ eb, float* __restrict__ ebsum,
                          float* __restrict__ repr)
{
    if (blockIdx.x == 0) {
        if (threadIdx.x < HID) {
            const int h = threadIdx.x;
            ebsum[h] = eb[h] + eb[HID + h] + eb[2*HID + h] + eb[3*HID + h];
        }
    } else {
        repr[(blockIdx.x - 1) * 256 + threadIdx.x] = 0.f;
    }
}

// ---------------------------------------------------------------------------------------
// Layer-0 node linear: 64-row blocks, 128 threads, 2 CTAs/SM. (validated)
// ---------------------------------------------------------------------------------------
__global__ __launch_bounds__(128, 2) void lin_mma(
    const uint16_t* __restrict__ xhi, const uint16_t* __restrict__ xlo,
    const uint16_t* __restrict__ wh, const uint16_t* __restrict__ wl,
    const float* __restrict__ bias,
    uint16_t* __restrict__ Yhi, uint16_t* __restrict__ Ylo, int D)
{
    extern __shared__ __align__(16) uint16_t lsm[];
    const uint32_t aX  = cvta_s(lsm);
    const uint32_t pX  = 64 * EPB;
    const uint32_t aW  = aX + 2 * 64 * EPB;
    const uint32_t pW  = 64 * EPB;

    const int m0 = blockIdx.x * 64;
    const int tid = threadIdx.x, warp = tid >> 5, lane = tid & 31;
    const int rT = tid >> 4, cT = tid & 15;
    const uint32_t lds_off = (lane & 15) * EPB + ((lane >> 4) << 4);

    const int dch = D >> 3;
    #pragma unroll
    for (int q = 0; q < 8; q++) {
        const int row = q * 8 + rT;
        if (cT < dch) {
            const size_t gi = (size_t)(m0 + row) * D + cT * 8;
            cp16(aX + row * EPB + cT * 16, xhi + gi);
            cp16(aX + pX + row * EPB + cT * 16, xlo + gi);
        }
    }
    #pragma unroll
    for (int q = 0; q < 8; q++) {
        const int row = q * 8 + rT;
        const size_t gi = (size_t)row * 128 + cT * 8;
        cp16(aW + row * EPB + cT * 16, wh + gi);
        cp16(aW + pW + row * EPB + cT * 16, wl + gi);
    }
    CP_COMMIT(); CP_WAIT(0); __syncthreads();

    float macc[16][4];
    #pragma unroll
    for (int j = 0; j < 16; j++)
        #pragma unroll
        for (int t = 0; t < 4; t++) macc[j][t] = 0.f;

    for (int dc = 0; dc < (D >> 4); dc++) {
        uint32_t ah[4], al[4];
        const uint32_t axo = aX + (warp * 16 + (lane & 15)) * EPB + dc * 32 + ((lane >> 4) << 4);
        ldsm_x4(ah, axo);
        ldsm_x4(al, axo + pX);
        const uint32_t wb = aW + dc * 16 * EPB + lds_off;
        #pragma unroll
        for (int jj = 0; jj < 8; jj++) {
            uint32_t bh[4], bl[4];
            ldsm_x4_t(bh, wb + jj * 32);
            ldsm_x4_t(bl, wb + pW + jj * 32);
            #pragma unroll
            for (int tp = 0; tp < 2; tp++) {
                mma_f16(macc[2*jj+tp], ah, &bh[2*tp]);
                mma_f16(macc[2*jj+tp], ah, &bl[2*tp]);
                mma_f16(macc[2*jj+tp], al, &bh[2*tp]);
            }
        }
    }

    const int r0 = m0 + warp * 16 + (lane >> 2);
    #pragma unroll
    for (int j = 0; j < 16; j++) {
        const int col = j * 8 + (lane & 3) * 2;
        const float2 bb = *(const float2*)&bias[col];
        const float v0 = macc[j][0] + bb.x, v1 = macc[j][1] + bb.y;
        const float v2 = macc[j][2] + bb.x, v3 = macc[j][3] + bb.y;
        const size_t o0 = (size_t)r0 * HID + col;
        const size_t o1 = o0 + 8 * HID;
        uint16_t h0,l0,h1,l1;
        splith(v0,h0,l0); splith(v1,h1,l1);
        ((uint32_t*)Yhi)[o0 >> 1] = packu(h0,h1);
        ((uint32_t*)Ylo)[o0 >> 1] = packu(l0,l1);
        splith(v2,h0,l0); splith(v3,h1,l1);
        ((uint32_t*)Yhi)[o1 >> 1] = packu(h0,h1);
        ((uint32_t*)Ylo)[o1 >> 1] = packu(l0,l1);
    }
}

// ---------------------------------------------------------------------------------------
// Fused MP + LN + ReLU + (mode 0) next node linear | (mode 1) readout accumulation.
// Bond-PAIRED GEMM1: one pass over mc serves two adj tiles per B read (halves smem B traffic).
// 64-row blocks, 128 threads, 104448 B smem -> 2 CTAs/SM.
// ---------------------------------------------------------------------------------------
__global__ __launch_bounds__(128, 2) void fused_mp(
    const float* __restrict__ adj, const uint16_t* __restrict__ yhi,
    const uint16_t* __restrict__ ylo, const uint16_t* __restrict__ wThi,
    const float* __restrict__ ebsum, const float* __restrict__ lng,
    const float* __restrict__ lnb,
    const uint16_t* __restrict__ wnh, const uint16_t* __restrict__ wnl,
    const float* __restrict__ nbias,
    uint16_t* __restrict__ youth, uint16_t* __restrict__ youtl,
    float* __restrict__ repr_g, int mode)
{
    extern __shared__ __align__(16) uint16_t dsm[];
    const uint32_t aY = cvta_s(dsm);
    const uint32_t aW = aY + 256 * EPB;
    const uint32_t pN = 128 * EPB;

    const int b = blockIdx.y;
    const int n0 = blockIdx.x * 64;
    const int tid = threadIdx.x, warp = tid >> 5, lane = tid & 31;
    const int wrow = n0 + warp * 16;
    const int rT = tid >> 4, cT = tid & 15;
    const int ar = lane >> 2, ac = (lane & 3) * 2;
    const uint32_t lds_off = (lane & 15) * EPB + ((lane >> 4) << 4);

    #pragma unroll
    for (int q = 0; q < 32; q++) {
        const int row = q * 8 + rT;
        cp16(aY + row * EPB + cT * 16, yhi + ((size_t)b * NN + row) * HID + cT * 8);
    }
    #pragma unroll
    for (int q = 0; q < 16; q++) {
        const int row = q * 8 + rT;
        cp16(aW + row * EPB + cT * 16, wThi + (size_t)row * 128 + cT * 8);
    }
    CP_COMMIT(); CP_WAIT(0); __syncthreads();

    float macc[16][4];
    #pragma unroll
    for (int j = 0; j < 16; j++)
        #pragma unroll
        for (int t = 0; t < 4; t++) macc[j][t] = 0.f;

#define STAGE_W(KK_) do {                                                                \
    _Pragma("unroll")                                                                    \
    for (int q_ = 0; q_ < 16; q_++) {                                                    \
        const int row_ = q_ * 8 + rT;                                                    \
        cp16(aW + row_ * EPB + cT * 16,                                                  \
             wThi + ((size_t)(KK_) << 14) + (size_t)row_ * 128 + cT * 8);                \
    }                                                                                    \
    CP_COMMIT();                                                                         \
} while(0)

#define GEMM2(NACC) do {                                                                 \
    _Pragma("unroll")                                                                    \
    for (int hc = 0; hc < 8; hc++) {                                                     \
        uint32_t ah_[4];                                                                 \
        ah_[0] = f22h2(NACC[2*hc][0],   NACC[2*hc][1]);                                  \
        ah_[1] = f22h2(NACC[2*hc][2],   NACC[2*hc][3]);                                  \
        ah_[2] = f22h2(NACC[2*hc+1][0], NACC[2*hc+1][1]);                                \
        ah_[3] = f22h2(NACC[2*hc+1][2], NACC[2*hc+1][3]);                                \
        const uint32_t wb_ = aW + hc * 16 * EPB + lds_off;                               \
        _Pragma("unroll")                                                                \
        for (int jj = 0; jj < 8; jj++) {                                                 \
            uint32_t bh_[4];                                                             \
            ldsm_x4_t(bh_, wb_ + jj * 32);                                               \
            mma_f16(macc[2*jj],   ah_, &bh_[0]);                                         \
            mma_f16(macc[2*jj+1], ah_, &bh_[2]);                                         \
        }                                                                                \
    }                                                                                    \
} while(0)

    for (int p = 0; p < 2; p++) {
        const int k0 = 2 * p;
        float nacc0[16][4], nacc1[16][4];
        #pragma unroll
        for (int j = 0; j < 16; j++)
            #pragma unroll
            for (int t = 0; t < 4; t++) { nacc0[j][t] = 0.f; nacc1[j][t] = 0.f; }

        const float* Ap0 = adj + (((size_t)(b * NK + k0)     * NN + wrow) * NN);
        const float* Ap1 = adj + (((size_t)(b * NK + k0 + 1) * NN + wrow) * NN);

        #pragma unroll
        for (int mc = 0; mc < 16; mc++) {
            const float* A0 = Ap0 + mc * 16;
            const float* A1 = Ap1 + mc * 16;
            uint32_t ah0[4], ah1[4];
            {
                float2 v;
                v = *(const float2*)(A0 + (size_t)ar * NN + ac);          ah0[0] = f22h2(v.x, v.y);
                v = *(const float2*)(A0 + (size_t)(ar+8) * NN + ac);      ah0[1] = f22h2(v.x, v.y);
                v = *(const float2*)(A0 + (size_t)ar * NN + ac + 8);      ah0[2] = f22h2(v.x, v.y);
                v = *(const float2*)(A0 + (size_t)(ar+8) * NN + ac + 8);  ah0[3] = f22h2(v.x, v.y);
                v = *(const float2*)(A1 + (size_t)ar * NN + ac);          ah1[0] = f22h2(v.x, v.y);
                v = *(const float2*)(A1 + (size_t)(ar+8) * NN + ac);      ah1[1] = f22h2(v.x, v.y);
                v = *(const float2*)(A1 + (size_t)ar * NN + ac + 8);      ah1[2] = f22h2(v.x, v.y);
                v = *(const float2*)(A1 + (size_t)(ar+8) * NN + ac + 8);  ah1[3] = f22h2(v.x, v.y);
            }
            const uint32_t yb = aY + mc * 16 * EPB + lds_off;
            #pragma unroll
            for (int jj = 0; jj < 8; jj++) {
                uint32_t bh[4];
                ldsm_x4_t(bh, yb + jj * 32);
                mma_f16(nacc0[2*jj],   ah0, &bh[0]);
                mma_f16(nacc0[2*jj+1], ah0, &bh[2]);
                mma_f16(nacc1[2*jj],   ah1, &bh[0]);
                mma_f16(nacc1[2*jj+1], ah1, &bh[2]);
            }
        }

        CP_WAIT(0); __syncthreads();          // W[k0] resident
        GEMM2(nacc0);
        __syncthreads();
        STAGE_W(k0 + 1);
        if (p == 1 && mode == 0) {            // stage Wnode into dead aY (separate group)
            #pragma unroll
            for (int q = 0; q < 16; q++) {
                const int row = q * 8 + rT;
                cp16(aY + row * EPB + cT * 16,      wnh + (size_t)row * 128 + cT * 8);
                cp16(aY + pN + row * EPB + cT * 16, wnl + (size_t)row * 128 + cT * 8);
            }
            CP_COMMIT();
            CP_WAIT(1);                       // W[k0+1] done; Wnode may still fly
        } else {
            CP_WAIT(0);
        }
        __syncthreads();
        GEMM2(nacc1);
        __syncthreads();
        if (p == 0) STAGE_W(2);               // overlaps next pair's GEMM1
    }

    // -------- epilogue: residual + ebsum + LN + ReLU --------
    const int r0 = wrow + (lane >> 2);
    const int r1 = r0 + 8;
    const uint32_t* yh32 = (const uint32_t*)yhi;
    const uint32_t* yl32 = (const uint32_t*)ylo;
    float s0 = 0.f, q0 = 0.f, s1 = 0.f, q1 = 0.f;
    #pragma unroll
    for (int j = 0; j < 16; j++) {
        const int col = j * 8 + (lane & 3) * 2;
        const float2 e = *(const float2*)&ebsum[col];
        const size_t w0 = ((size_t)b * NN + r0) * HID + col;
        const size_t w1 = ((size_t)b * NN + r1) * HID + col;
        const float2 y0 = h2pairf(yh32[w0 >> 1], yl32[w0 >> 1]);
        const float2 y1 = h2pairf(yh32[w1 >> 1], yl32[w1 >> 1]);
        macc[j][0] += y0.x + e.x;  macc[j][1] += y0.y + e.y;
        macc[j][2] += y1.x + e.x;  macc[j][3] += y1.y + e.y;
        s0 += macc[j][0] + macc[j][1];
        q0 += macc[j][0]*macc[j][0] + macc[j][1]*macc[j][1];
        s1 += macc[j][2] + macc[j][3];
        q1 += macc[j][2]*macc[j][2] + macc[j][3]*macc[j][3];
    }
    #pragma unroll
    for (int d = 1; d <= 2; d <<= 1) {
        s0 += __shfl_xor_sync(0xffffffffu, s0, d);
        q0 += __shfl_xor_sync(0xffffffffu, q0, d);
        s1 += __shfl_xor_sync(0xffffffffu, s1, d);
        q1 += __shfl_xor_sync(0xffffffffu, q1, d);
    }
    const float mu0 = s0 * (1.f/HID), mu1 = s1 * (1.f/HID);
    const float ri0 = rsqrtf(q0 * (1.f/HID) - mu0*mu0 + LN_EPS);
    const float ri1 = rsqrtf(q1 * (1.f/HID) - mu1*mu1 + LN_EPS);

    #pragma unroll
    for (int j = 0; j < 16; j++) {
        const int col = j * 8 + (lane & 3) * 2;
        const float2 gg = *(const float2*)&lng[col];
        const float2 bb = *(const float2*)&lnb[col];
        macc[j][0] = fmaxf((macc[j][0]-mu0)*ri0*gg.x + bb.x, 0.f);
        macc[j][1] = fmaxf((macc[j][1]-mu0)*ri0*gg.y + bb.y, 0.f);
        macc[j][2] = fmaxf((macc[j][2]-mu1)*ri1*gg.x + bb.x, 0.f);
        macc[j][3] = fmaxf((macc[j][3]-mu1)*ri1*gg.y + bb.y, 0.f);
    }

    if (mode == 1) {
        #pragma unroll
        for (int j = 0; j < 16; j++) {
            float v0 = macc[j][0] + macc[j][2];
            float v1 = macc[j][1] + macc[j][3];
            #pragma unroll
            for (int d = 4; d <= 16; d <<= 1) {
                v0 += __shfl_down_sync(0xffffffffu, v0, d);
                v1 += __shfl_down_sync(0xffffffffu, v1, d);
            }
            if ((lane >> 2) == 0) {
                const int col = j * 8 + lane * 2;
                atomicAdd(&repr_g[b * HID + col],     v0);
                atomicAdd(&repr_g[b * HID + col + 1], v1);
            }
        }
        return;
    }

    // -------- GEMM3: y' = x @ Wnode^T + b (3-product, x split in-register) --------
    CP_WAIT(0); __syncthreads();

    float yacc[16][4];
    #pragma unroll
    for (int j = 0; j < 16; j++)
        #pragma unroll
        for (int t = 0; t < 4; t++) yacc[j][t] = 0.f;

    #pragma unroll
    for (int kc = 0; kc < 8; kc++) {
        uint32_t ahh[4], ahl[4];
        uint16_t h0,l0,h1,l1;
        splith(macc[2*kc][0],h0,l0);   splith(macc[2*kc][1],h1,l1);
        ahh[0]=packu(h0,h1); ahl[0]=packu(l0,l1);
        splith(macc[2*kc][2],h0,l0);   splith(macc[2*kc][3],h1,l1);
        ahh[1]=packu(h0,h1); ahl[1]=packu(l0,l1);
        splith(macc[2*kc+1][0],h0,l0); splith(macc[2*kc+1][1],h1,l1);
        ahh[2]=packu(h0,h1); ahl[2]=packu(l0,l1);
        splith(macc[2*kc+1][2],h0,l0); splith(macc[2*kc+1][3],h1,l1);
        ahh[3]=packu(h0,h1); ahl[3]=packu(l0,l1);
        const uint32_t wb = aY + kc * 16 * EPB + lds_off;
        #pragma unroll
        for (int jj = 0; jj < 8; jj++) {
            uint32_t bh[4], bl[4];
            ldsm_x4_t(bh, wb + jj * 32);
            ldsm_x4_t(bl, wb + pN + jj * 32);
            #pragma unroll
            for (int tp = 0; tp < 2; tp++) {
                mma_f16(yacc[2*jj+tp], ahh, &bh[2*tp]);
                mma_f16(yacc[2*jj+tp], ahh, &bl[2*tp]);
                mma_f16(yacc[2*jj+tp], ahl, &bh[2*tp]);
            }
        }
    }

    #pragma unroll
    for (int j = 0; j < 16; j++) {
        const int col = j * 8 + (lane & 3) * 2;
        const float2 bb = *(const float2*)&nbias[col];
        const float v0 = yacc[j][0] + bb.x, v1 = yacc[j][1] + bb.y;
        const float v2 = yacc[j][2] + bb.x, v3 = yacc[j][3] + bb.y;
        const size_t w0 = ((size_t)b * NN + r0) * HID + col;
        const size_t w1 = ((size_t)b * NN + r1) * HID + col;
        uint16_t h0,l0,h1,l1;
        splith(v0,h0,l0); splith(v1,h1,l1);
        ((uint32_t*)youth)[w0 >> 1] = packu(h0,h1);
        ((uint32_t*)youtl)[w0 >> 1] = packu(l0,l1);
        splith(v2,h0,l0); splith(v3,h1,l1);
        ((uint32_t*)youth)[w1 >> 1] = packu(h0,h1);
        ((uint32_t*)youtl)[w1 >> 1] = packu(l0,l1);
    }
#undef STAGE_W
#undef GEMM2
}

// ---------------------------------------------------------------------------------------
__global__ void out_gemv(const float* __restrict__ repr, const float* __restrict__ oW,
                         const float* __restrict__ ob, float* __restrict__ out)
{
    const int b = blockIdx.x;
    const int o = threadIdx.x;
    float acc = ob[o];
    const float* rp = repr + (size_t)b * HID;
    #pragma unroll 8
    for (int d = 0; d < HID; d++) acc += rp[d] * oW[o * HID + d];
    out[b * NOUT + o] = acc;
}

// ---------------------------------------------------------------------------------------
extern "C" void kernel_launch(void* const* d_in, const int* in_sizes, int n_in,
                              void* d_out, int out_size)
{
    const float* feat = (const float*)d_in[0];
    const float* adj  = (const float*)d_in[1];
    const float* nW[3] = {(const float*)d_in[2], (const float*)d_in[4], (const float*)d_in[6]};
    const float* nb[3] = {(const float*)d_in[3], (const float*)d_in[5], (const float*)d_in[7]};
    const float* eW  = (const float*)d_in[8];
    const float* ebp = (const float*)d_in[9];
    const float* lng = (const float*)d_in[10];
    const float* lnb = (const float*)d_in[11];
    const float* oW  = (const float*)d_in[12];
    const float* ob  = (const float*)d_in[13];

    float *ebs, *repr;
    uint16_t *yAh, *yAl, *yBh, *yBl, *fhi, *flo, *ewh, *nwh, *nwl;
    cudaGetSymbolAddress((void**)&yAh, g_yhi);
    cudaGetSymbolAddress((void**)&yAl, g_ylo);
    cudaGetSymbolAddress((void**)&yBh, g_xhi);
    cudaGetSymbolAddress((void**)&yBl, g_xlo);
    cudaGetSymbolAddress((void**)&fhi, g_fhi);
    cudaGetSymbolAddress((void**)&flo, g_flo);
    cudaGetSymbolAddress((void**)&ewh, g_ewh);
    cudaGetSymbolAddress((void**)&nwh, g_nwh);
    cudaGetSymbolAddress((void**)&nwl, g_nwl);
    cudaGetSymbolAddress((void**)&ebs, g_ebsum);
    cudaGetSymbolAddress((void**)&repr, g_repr);

    const int FUSED_SMEM = (256 + 128) * EPB;   // 104448 B -> 2 CTAs/SM
    const int LIN_SMEM   = 4 * 64 * EPB;        // 69632 B  -> 2 CTAs/SM
    cudaFuncSetAttribute(fused_mp, cudaFuncAttributeMaxDynamicSharedMemorySize, FUSED_SMEM);
    cudaFuncSetAttribute(lin_mma,  cudaFuncAttributeMaxDynamicSharedMemorySize, LIN_SMEM);

    prep_weights<<<416, 256>>>(nW[0], nW[1], nW[2], eW, nwh, nwl, ewh);
    prep_feat<<<MM*IND/256, 256>>>(feat, fhi, flo);
    prep_misc<<<129, 256>>>(ebp, ebs, repr);

    lin_mma<<<MM/64, 128, LIN_SMEM>>>(fhi, flo, nwh, nwl, nb[0], yAh, yAl, IND);
    fused_mp<<<dim3(4, BB), 128, FUSED_SMEM>>>(adj, yAh, yAl, ewh, ebs,
                                               lng, lnb,
                                               nwh + 16384, nwl + 16384, nb[1],
                                               yBh, yBl, repr, 0);
    fused_mp<<<dim3(4, BB), 128, FUSED_SMEM>>>(adj, yBh, yBl, ewh, ebs,
                                               lng + HID, lnb + HID,
                                               nwh + 32768, nwl + 32768, nb[2],
                                               yAh, yAl, repr, 0);
    fused_mp<<<dim3(4, BB), 128, FUSED_SMEM>>>(adj, yAh, yAl, ewh, ebs,
                                               lng + 2*HID, lnb + 2*HID,
                                               nwh, nwl, nb[0],
                                               yBh, yBl, repr, 1);
    out_gemv<<<BB, NOUT>>>(repr, oW, ob, (float*)d_out);
}

// round 17
// speedup vs baseline: 1.0289x; 1.0289x over previous
#include <cuda_runtime.h>
#include <cuda_fp16.h>
#include <cstdint>

#define BB 256
#define NN 256
#define IND 64
#define HID 128
#define NOUT 16
#define NL 3
#define NK 4
#define MM (BB*NN)
#define LN_EPS 1e-5f
#define EP 136
#define EPB (EP*2)

__device__ uint16_t g_yhi[(size_t)MM * HID];
__device__ uint16_t g_ylo[(size_t)MM * HID];
__device__ uint16_t g_xhi[(size_t)MM * HID];
__device__ uint16_t g_xlo[(size_t)MM * HID];
__device__ uint16_t g_fhi[(size_t)MM * IND];
__device__ uint16_t g_flo[(size_t)MM * IND];
__device__ uint16_t g_ewh[(size_t)NK * HID * HID];
__device__ uint16_t g_nwh[(size_t)NL * HID * HID];
__device__ uint16_t g_nwl[(size_t)NL * HID * HID];
__device__ float    g_ebsum[HID];
__device__ float    g_repr[(size_t)BB * HID];

__device__ __forceinline__ void splith(float a, uint16_t &h, uint16_t &l) {
    __half hh = __float2half_rn(a);
    __half ll = __float2half_rn(a - __half2float(hh));
    h = __half_as_ushort(hh); l = __half_as_ushort(ll);
}
__device__ __forceinline__ uint32_t packu(uint16_t a, uint16_t b) {
    return (uint32_t)a | ((uint32_t)b << 16);
}
__device__ __forceinline__ uint32_t f22h2(float x, float y) {
    __half2 h = __floats2half2_rn(x, y);
    return *(uint32_t*)&h;
}
__device__ __forceinline__ float2 h2pairf(uint32_t hbits, uint32_t lbits) {
    float2 a = __half22float2(*(__half2*)&hbits);
    float2 b = __half22float2(*(__half2*)&lbits);
    return make_float2(a.x + b.x, a.y + b.y);
}
__device__ __forceinline__ uint32_t cvta_s(const void* p) {
    return (uint32_t)__cvta_generic_to_shared(p);
}
__device__ __forceinline__ void ldsm_x4(uint32_t* r, uint32_t addr) {
    asm volatile("ldmatrix.sync.aligned.m8n8.x4.shared.b16 {%0,%1,%2,%3}, [%4];"
                 : "=r"(r[0]), "=r"(r[1]), "=r"(r[2]), "=r"(r[3]) : "r"(addr));
}
__device__ __forceinline__ void ldsm_x4_t(uint32_t* r, uint32_t addr) {
    asm volatile("ldmatrix.sync.aligned.m8n8.x4.trans.shared.b16 {%0,%1,%2,%3}, [%4];"
                 : "=r"(r[0]), "=r"(r[1]), "=r"(r[2]), "=r"(r[3]) : "r"(addr));
}
__device__ __forceinline__ void mma_f16(float* c, const uint32_t* a, const uint32_t* b) {
    asm volatile("mma.sync.aligned.m16n8k16.row.col.f32.f16.f16.f32 "
                 "{%0,%1,%2,%3}, {%4,%5,%6,%7}, {%8,%9}, {%0,%1,%2,%3};"
                 : "+f"(c[0]), "+f"(c[1]), "+f"(c[2]), "+f"(c[3])
                 : "r"(a[0]), "r"(a[1]), "r"(a[2]), "r"(a[3]), "r"(b[0]), "r"(b[1]));
}
__device__ __forceinline__ void cp16(uint32_t dst, const void* src) {
    asm volatile("cp.async.cg.shared.global [%0], [%1], 16;" :: "r"(dst), "l"(src));
}
#define CP_COMMIT() asm volatile("cp.async.commit_group;")
#define CP_WAIT(n)  asm volatile("cp.async.wait_group %0;" :: "n"(n))

// ---------------------------------------------------------------------------------------
// Single merged prep launch: [0,416) weights | [416, 416+16384) feat | tail: ebsum+repr
// ---------------------------------------------------------------------------------------
#define FEAT_BLKS (MM*IND/256)
__global__ void prep_all(const float* __restrict__ nW0, const float* __restrict__ nW1,
                         const float* __restrict__ nW2, const float* __restrict__ eW,
                         const float* __restrict__ feat, const float* __restrict__ eb,
                         uint16_t* __restrict__ nwh, uint16_t* __restrict__ nwl,
                         uint16_t* __restrict__ ewh,
                         uint16_t* __restrict__ fhi, uint16_t* __restrict__ flo,
                         float* __restrict__ ebsum, float* __restrict__ repr)
{
    const int bid = blockIdx.x, tid = threadIdx.x;
    if (bid < 32) {                                   // nW0: 128x64
        const int idx = bid * 256 + tid;
        const int o = idx >> 6, d = idx & 63;
        uint16_t h, l; splith(nW0[idx], h, l);
        nwh[d * 128 + o] = h; nwl[d * 128 + o] = l;
    } else if (bid < 96) {                            // nW1
        const int idx = (bid - 32) * 256 + tid;
        const int o = idx >> 7, d = idx & 127;
        uint16_t h, l; splith(nW1[idx], h, l);
        nwh[16384 + d * 128 + o] = h; nwl[16384 + d * 128 + o] = l;
    } else if (bid < 160) {                           // nW2
        const int idx = (bid - 96) * 256 + tid;
        const int o = idx >> 7, d = idx & 127;
        uint16_t h, l; splith(nW2[idx], h, l);
        nwh[32768 + d * 128 + o] = h; nwl[32768 + d * 128 + o] = l;
    } else if (bid < 416) {                           // eW hi
        const int idx = (bid - 160) * 256 + tid;
        const int k = idx >> 14, rem = idx & 16383;
        const int o = rem >> 7, d = rem & 127;
        ewh[(k << 14) + d * 128 + o] = __half_as_ushort(__float2half_rn(eW[idx]));
    } else if (bid < 416 + FEAT_BLKS) {               // feat split
        const int idx = (bid - 416) * 256 + tid;
        uint16_t h, l; splith(feat[idx], h, l);
        fhi[idx] = h; flo[idx] = l;
    } else if (bid == 416 + FEAT_BLKS) {              // ebsum
        if (tid < HID)
            ebsum[tid] = eb[tid] + eb[HID + tid] + eb[2*HID + tid] + eb[3*HID + tid];
    } else {                                          // zero repr (128 blocks)
        repr[(size_t)(bid - 417 - FEAT_BLKS) * 256 + tid] = 0.f;
    }
}

// ---------------------------------------------------------------------------------------
// Layer-0 node linear: 64-row blocks, 128 threads, 2 CTAs/SM. (validated)
// ---------------------------------------------------------------------------------------
__global__ __launch_bounds__(128, 2) void lin_mma(
    const uint16_t* __restrict__ xhi, const uint16_t* __restrict__ xlo,
    const uint16_t* __restrict__ wh, const uint16_t* __restrict__ wl,
    const float* __restrict__ bias,
    uint16_t* __restrict__ Yhi, uint16_t* __restrict__ Ylo, int D)
{
    extern __shared__ __align__(16) uint16_t lsm[];
    const uint32_t aX  = cvta_s(lsm);
    const uint32_t pX  = 64 * EPB;
    const uint32_t aW  = aX + 2 * 64 * EPB;
    const uint32_t pW  = 64 * EPB;

    const int m0 = blockIdx.x * 64;
    const int tid = threadIdx.x, warp = tid >> 5, lane = tid & 31;
    const int rT = tid >> 4, cT = tid & 15;
    const uint32_t lds_off = (lane & 15) * EPB + ((lane >> 4) << 4);

    const int dch = D >> 3;
    #pragma unroll
    for (int q = 0; q < 8; q++) {
        const int row = q * 8 + rT;
        if (cT < dch) {
            const size_t gi = (size_t)(m0 + row) * D + cT * 8;
            cp16(aX + row * EPB + cT * 16, xhi + gi);
            cp16(aX + pX + row * EPB + cT * 16, xlo + gi);
        }
    }
    #pragma unroll
    for (int q = 0; q < 8; q++) {
        const int row = q * 8 + rT;
        const size_t gi = (size_t)row * 128 + cT * 8;
        cp16(aW + row * EPB + cT * 16, wh + gi);
        cp16(aW + pW + row * EPB + cT * 16, wl + gi);
    }
    CP_COMMIT(); CP_WAIT(0); __syncthreads();

    float macc[16][4];
    #pragma unroll
    for (int j = 0; j < 16; j++)
        #pragma unroll
        for (int t = 0; t < 4; t++) macc[j][t] = 0.f;

    for (int dc = 0; dc < (D >> 4); dc++) {
        uint32_t ah[4], al[4];
        const uint32_t axo = aX + (warp * 16 + (lane & 15)) * EPB + dc * 32 + ((lane >> 4) << 4);
        ldsm_x4(ah, axo);
        ldsm_x4(al, axo + pX);
        const uint32_t wb = aW + dc * 16 * EPB + lds_off;
        #pragma unroll
        for (int jj = 0; jj < 8; jj++) {
            uint32_t bh[4], bl[4];
            ldsm_x4_t(bh, wb + jj * 32);
            ldsm_x4_t(bl, wb + pW + jj * 32);
            #pragma unroll
            for (int tp = 0; tp < 2; tp++) {
                mma_f16(macc[2*jj+tp], ah, &bh[2*tp]);
                mma_f16(macc[2*jj+tp], ah, &bl[2*tp]);
                mma_f16(macc[2*jj+tp], al, &bh[2*tp]);
            }
        }
    }

    const int r0 = m0 + warp * 16 + (lane >> 2);
    #pragma unroll
    for (int j = 0; j < 16; j++) {
        const int col = j * 8 + (lane & 3) * 2;
        const float2 bb = *(const float2*)&bias[col];
        const float v0 = macc[j][0] + bb.x, v1 = macc[j][1] + bb.y;
        const float v2 = macc[j][2] + bb.x, v3 = macc[j][3] + bb.y;
        const size_t o0 = (size_t)r0 * HID + col;
        const size_t o1 = o0 + 8 * HID;
        uint16_t h0,l0,h1,l1;
        splith(v0,h0,l0); splith(v1,h1,l1);
        ((uint32_t*)Yhi)[o0 >> 1] = packu(h0,h1);
        ((uint32_t*)Ylo)[o0 >> 1] = packu(l0,l1);
        splith(v2,h0,l0); splith(v3,h1,l1);
        ((uint32_t*)Yhi)[o1 >> 1] = packu(h0,h1);
        ((uint32_t*)Ylo)[o1 >> 1] = packu(l0,l1);
    }
}

// ---------------------------------------------------------------------------------------
// Fused MP + LN + ReLU + (mode 0) next node linear | (mode 1) readout accumulation.
// R15-validated: 64-row blocks, 128 threads, 104448 B smem -> 2 CTAs/SM.
// ---------------------------------------------------------------------------------------
__global__ __launch_bounds__(128, 2) void fused_mp(
    const float* __restrict__ adj, const uint16_t* __restrict__ yhi,
    const uint16_t* __restrict__ ylo, const uint16_t* __restrict__ wThi,
    const float* __restrict__ ebsum, const float* __restrict__ lng,
    const float* __restrict__ lnb,
    const uint16_t* __restrict__ wnh, const uint16_t* __restrict__ wnl,
    const float* __restrict__ nbias,
    uint16_t* __restrict__ youth, uint16_t* __restrict__ youtl,
    float* __restrict__ repr_g, int mode)
{
    extern __shared__ __align__(16) uint16_t dsm[];
    const uint32_t aY = cvta_s(dsm);
    const uint32_t aW = aY + 256 * EPB;
    const uint32_t pN = 128 * EPB;

    const int b = blockIdx.y;
    const int n0 = blockIdx.x * 64;
    const int tid = threadIdx.x, warp = tid >> 5, lane = tid & 31;
    const int wrow = n0 + warp * 16;
    const int rT = tid >> 4, cT = tid & 15;
    const int ar = lane >> 2, ac = (lane & 3) * 2;
    const uint32_t lds_off = (lane & 15) * EPB + ((lane >> 4) << 4);

    float2 adjP[2][4];
#define ADJ_LD(BUF_, KK_, MCC_) do {                                                     \
    const float* An_ = adj + (((size_t)(b * NK + (KK_)) * NN + wrow) * NN) + (MCC_) * 16;\
    adjP[BUF_][0] = *(const float2*)(An_ + (size_t)ar * NN + ac);                        \
    adjP[BUF_][1] = *(const float2*)(An_ + (size_t)(ar+8) * NN + ac);                    \
    adjP[BUF_][2] = *(const float2*)(An_ + (size_t)ar * NN + ac + 8);                    \
    adjP[BUF_][3] = *(const float2*)(An_ + (size_t)(ar+8) * NN + ac + 8);                \
} while(0)

    #pragma unroll
    for (int q = 0; q < 32; q++) {
        const int row = q * 8 + rT;
        cp16(aY + row * EPB + cT * 16, yhi + ((size_t)b * NN + row) * HID + cT * 8);
    }
    #pragma unroll
    for (int q = 0; q < 16; q++) {
        const int row = q * 8 + rT;
        cp16(aW + row * EPB + cT * 16, wThi + (size_t)row * 128 + cT * 8);
    }
    CP_COMMIT();
    ADJ_LD(0, 0, 0);
    ADJ_LD(1, 0, 1);
    CP_WAIT(0); __syncthreads();

    float macc[16][4];
    #pragma unroll
    for (int j = 0; j < 16; j++)
        #pragma unroll
        for (int t = 0; t < 4; t++) macc[j][t] = 0.f;

    for (int k = 0; k < NK; k++) {
        float nacc[16][4];
        #pragma unroll
        for (int j = 0; j < 16; j++)
            #pragma unroll
            for (int t = 0; t < 4; t++) nacc[j][t] = 0.f;

        #pragma unroll
        for (int mc = 0; mc < 16; mc++) {
            uint32_t ah[4];
            #pragma unroll
            for (int q = 0; q < 4; q++)
                ah[q] = f22h2(adjP[mc&1][q].x, adjP[mc&1][q].y);
            if (mc < 14) {
                ADJ_LD(mc&1, k, mc + 2);
            } else if (k < NK - 1) {
                ADJ_LD(mc&1, k + 1, mc - 14);
            }
            const uint32_t yb = aY + mc * 16 * EPB + lds_off;
            #pragma unroll
            for (int jj = 0; jj < 8; jj++) {
                uint32_t bh[4];
                ldsm_x4_t(bh, yb + jj * 32);
                mma_f16(nacc[2*jj],   ah, &bh[0]);
                mma_f16(nacc[2*jj+1], ah, &bh[2]);
            }
        }

        CP_WAIT(0); __syncthreads();

        if (k == NK - 1 && mode == 0) {
            #pragma unroll
            for (int q = 0; q < 16; q++) {
                const int row = q * 8 + rT;
                cp16(aY + row * EPB + cT * 16,      wnh + (size_t)row * 128 + cT * 8);
                cp16(aY + pN + row * EPB + cT * 16, wnl + (size_t)row * 128 + cT * 8);
            }
            CP_COMMIT();
        }

        #pragma unroll
        for (int hc = 0; hc < 8; hc++) {
            uint32_t ah[4];
            ah[0] = f22h2(nacc[2*hc][0],   nacc[2*hc][1]);
            ah[1] = f22h2(nacc[2*hc][2],   nacc[2*hc][3]);
            ah[2] = f22h2(nacc[2*hc+1][0], nacc[2*hc+1][1]);
            ah[3] = f22h2(nacc[2*hc+1][2], nacc[2*hc+1][3]);
            const uint32_t wb = aW + hc * 16 * EPB + lds_off;
            #pragma unroll
            for (int jj = 0; jj < 8; jj++) {
                uint32_t bh[4];
                ldsm_x4_t(bh, wb + jj * 32);
                mma_f16(macc[2*jj],   ah, &bh[0]);
                mma_f16(macc[2*jj+1], ah, &bh[2]);
            }
        }
        __syncthreads();
        if (k < NK - 1) {
            #pragma unroll
            for (int q = 0; q < 16; q++) {
                const int row = q * 8 + rT;
                cp16(aW + row * EPB + cT * 16,
                     wThi + ((size_t)(k + 1) << 14) + (size_t)row * 128 + cT * 8);
            }
            CP_COMMIT();
        }
    }

    // -------- epilogue: residual + ebsum + LN + ReLU --------
    const int r0 = wrow + (lane >> 2);
    const int r1 = r0 + 8;
    const uint32_t* yh32 = (const uint32_t*)yhi;
    const uint32_t* yl32 = (const uint32_t*)ylo;
    float s0 = 0.f, q0 = 0.f, s1 = 0.f, q1 = 0.f;
    #pragma unroll
    for (int j = 0; j < 16; j++) {
        const int col = j * 8 + (lane & 3) * 2;
        const float2 e = *(const float2*)&ebsum[col];
        const size_t w0 = ((size_t)b * NN + r0) * HID + col;
        const size_t w1 = ((size_t)b * NN + r1) * HID + col;
        const float2 y0 = h2pairf(yh32[w0 >> 1], yl32[w0 >> 1]);
        const float2 y1 = h2pairf(yh32[w1 >> 1], yl32[w1 >> 1]);
        macc[j][0] += y0.x + e.x;  macc[j][1] += y0.y + e.y;
        macc[j][2] += y1.x + e.x;  macc[j][3] += y1.y + e.y;
        s0 += macc[j][0] + macc[j][1];
        q0 += macc[j][0]*macc[j][0] + macc[j][1]*macc[j][1];
        s1 += macc[j][2] + macc[j][3];
        q1 += macc[j][2]*macc[j][2] + macc[j][3]*macc[j][3];
    }
    #pragma unroll
    for (int d = 1; d <= 2; d <<= 1) {
        s0 += __shfl_xor_sync(0xffffffffu, s0, d);
        q0 += __shfl_xor_sync(0xffffffffu, q0, d);
        s1 += __shfl_xor_sync(0xffffffffu, s1, d);
        q1 += __shfl_xor_sync(0xffffffffu, q1, d);
    }
    const float mu0 = s0 * (1.f/HID), mu1 = s1 * (1.f/HID);
    const float ri0 = rsqrtf(q0 * (1.f/HID) - mu0*mu0 + LN_EPS);
    const float ri1 = rsqrtf(q1 * (1.f/HID) - mu1*mu1 + LN_EPS);

    #pragma unroll
    for (int j = 0; j < 16; j++) {
        const int col = j * 8 + (lane & 3) * 2;
        const float2 gg = *(const float2*)&lng[col];
        const float2 bb = *(const float2*)&lnb[col];
        macc[j][0] = fmaxf((macc[j][0]-mu0)*ri0*gg.x + bb.x, 0.f);
        macc[j][1] = fmaxf((macc[j][1]-mu0)*ri0*gg.y + bb.y, 0.f);
        macc[j][2] = fmaxf((macc[j][2]-mu1)*ri1*gg.x + bb.x, 0.f);
        macc[j][3] = fmaxf((macc[j][3]-mu1)*ri1*gg.y + bb.y, 0.f);
    }

    if (mode == 1) {
        #pragma unroll
        for (int j = 0; j < 16; j++) {
            float v0 = macc[j][0] + macc[j][2];
            float v1 = macc[j][1] + macc[j][3];
            #pragma unroll
            for (int d = 4; d <= 16; d <<= 1) {
                v0 += __shfl_down_sync(0xffffffffu, v0, d);
                v1 += __shfl_down_sync(0xffffffffu, v1, d);
            }
            if ((lane >> 2) == 0) {
                const int col = j * 8 + lane * 2;
                atomicAdd(&repr_g[b * HID + col],     v0);
                atomicAdd(&repr_g[b * HID + col + 1], v1);
            }
        }
        return;
    }

    // -------- GEMM3: y' = x @ Wnode^T + b (3-product, x split in-register) --------
    CP_WAIT(0); __syncthreads();

    float yacc[16][4];
    #pragma unroll
    for (int j = 0; j < 16; j++)
        #pragma unroll
        for (int t = 0; t < 4; t++) yacc[j][t] = 0.f;

    #pragma unroll
    for (int kc = 0; kc < 8; kc++) {
        uint32_t ahh[4], ahl[4];
        uint16_t h0,l0,h1,l1;
        splith(macc[2*kc][0],h0,l0);   splith(macc[2*kc][1],h1,l1);
        ahh[0]=packu(h0,h1); ahl[0]=packu(l0,l1);
        splith(macc[2*kc][2],h0,l0);   splith(macc[2*kc][3],h1,l1);
        ahh[1]=packu(h0,h1); ahl[1]=packu(l0,l1);
        splith(macc[2*kc+1][0],h0,l0); splith(macc[2*kc+1][1],h1,l1);
        ahh[2]=packu(h0,h1); ahl[2]=packu(l0,l1);
        splith(macc[2*kc+1][2],h0,l0); splith(macc[2*kc+1][3],h1,l1);
        ahh[3]=packu(h0,h1); ahl[3]=packu(l0,l1);
        const uint32_t wb = aY + kc * 16 * EPB + lds_off;
        #pragma unroll
        for (int jj = 0; jj < 8; jj++) {
            uint32_t bh[4], bl[4];
            ldsm_x4_t(bh, wb + jj * 32);
            ldsm_x4_t(bl, wb + pN + jj * 32);
            #pragma unroll
            for (int tp = 0; tp < 2; tp++) {
                mma_f16(yacc[2*jj+tp], ahh, &bh[2*tp]);
                mma_f16(yacc[2*jj+tp], ahh, &bl[2*tp]);
                mma_f16(yacc[2*jj+tp], ahl, &bh[2*tp]);
            }
        }
    }

    #pragma unroll
    for (int j = 0; j < 16; j++) {
        const int col = j * 8 + (lane & 3) * 2;
        const float2 bb = *(const float2*)&nbias[col];
        const float v0 = yacc[j][0] + bb.x, v1 = yacc[j][1] + bb.y;
        const float v2 = yacc[j][2] + bb.x, v3 = yacc[j][3] + bb.y;
        const size_t w0 = ((size_t)b * NN + r0) * HID + col;
        const size_t w1 = ((size_t)b * NN + r1) * HID + col;
        uint16_t h0,l0,h1,l1;
        splith(v0,h0,l0); splith(v1,h1,l1);
        ((uint32_t*)youth)[w0 >> 1] = packu(h0,h1);
        ((uint32_t*)youtl)[w0 >> 1] = packu(l0,l1);
        splith(v2,h0,l0); splith(v3,h1,l1);
        ((uint32_t*)youth)[w1 >> 1] = packu(h0,h1);
        ((uint32_t*)youtl)[w1 >> 1] = packu(l0,l1);
    }
#undef ADJ_LD
}

// ---------------------------------------------------------------------------------------
__global__ void out_gemv(const float* __restrict__ repr, const float* __restrict__ oW,
                         const float* __restrict__ ob, float* __restrict__ out)
{
    const int b = blockIdx.x;
    const int o = threadIdx.x;
    float acc = ob[o];
    const float* rp = repr + (size_t)b * HID;
    #pragma unroll 8
    for (int d = 0; d < HID; d++) acc += rp[d] * oW[o * HID + d];
    out[b * NOUT + o] = acc;
}

// ---------------------------------------------------------------------------------------
extern "C" void kernel_launch(void* const* d_in, const int* in_sizes, int n_in,
                              void* d_out, int out_size)
{
    const float* feat = (const float*)d_in[0];
    const float* adj  = (const float*)d_in[1];
    const float* nW[3] = {(const float*)d_in[2], (const float*)d_in[4], (const float*)d_in[6]};
    const float* nb[3] = {(const float*)d_in[3], (const float*)d_in[5], (const float*)d_in[7]};
    const float* eW  = (const float*)d_in[8];
    const float* ebp = (const float*)d_in[9];
    const float* lng = (const float*)d_in[10];
    const float* lnb = (const float*)d_in[11];
    const float* oW  = (const float*)d_in[12];
    const float* ob  = (const float*)d_in[13];

    float *ebs, *repr;
    uint16_t *yAh, *yAl, *yBh, *yBl, *fhi, *flo, *ewh, *nwh, *nwl;
    cudaGetSymbolAddress((void**)&yAh, g_yhi);
    cudaGetSymbolAddress((void**)&yAl, g_ylo);
    cudaGetSymbolAddress((void**)&yBh, g_xhi);
    cudaGetSymbolAddress((void**)&yBl, g_xlo);
    cudaGetSymbolAddress((void**)&fhi, g_fhi);
    cudaGetSymbolAddress((void**)&flo, g_flo);
    cudaGetSymbolAddress((void**)&ewh, g_ewh);
    cudaGetSymbolAddress((void**)&nwh, g_nwh);
    cudaGetSymbolAddress((void**)&nwl, g_nwl);
    cudaGetSymbolAddress((void**)&ebs, g_ebsum);
    cudaGetSymbolAddress((void**)&repr, g_repr);

    const int FUSED_SMEM = (256 + 128) * EPB;   // 104448 B -> 2 CTAs/SM
    const int LIN_SMEM   = 4 * 64 * EPB;        // 69632 B  -> 2 CTAs/SM
    cudaFuncSetAttribute(fused_mp, cudaFuncAttributeMaxDynamicSharedMemorySize, FUSED_SMEM);
    cudaFuncSetAttribute(lin_mma,  cudaFuncAttributeMaxDynamicSharedMemorySize, LIN_SMEM);

    // one merged prep launch: 416 weight blocks + FEAT_BLKS feat blocks + 1 ebsum + 128 repr
    prep_all<<<416 + FEAT_BLKS + 129, 256>>>(nW[0], nW[1], nW[2], eW, feat, ebp,
                                             nwh, nwl, ewh, fhi, flo, ebs, repr);

    lin_mma<<<MM/64, 128, LIN_SMEM>>>(fhi, flo, nwh, nwl, nb[0], yAh, yAl, IND);
    fused_mp<<<dim3(4, BB), 128, FUSED_SMEM>>>(adj, yAh, yAl, ewh, ebs,
                                               lng, lnb,
                                               nwh + 16384, nwl + 16384, nb[1],
                                               yBh, yBl, repr, 0);
    fused_mp<<<dim3(4, BB), 128, FUSED_SMEM>>>(adj, yBh, yBl, ewh, ebs,
                                               lng + HID, lnb + HID,
                                               nwh + 32768, nwl + 32768, nb[2],
                                               yAh, yAl, repr, 0);
    fused_mp<<<dim3(4, BB), 128, FUSED_SMEM>>>(adj, yAh, yAl, ewh, ebs,
                                               lng + 2*HID, lnb + 2*HID,
                                               nwh, nwl, nb[0],
                                               yBh, yBl, repr, 1);
    out_gemv<<<BB, NOUT>>>(repr, oW, ob, (float*)d_out);
}